// round 2
// baseline (speedup 1.0000x reference)
#include <cuda_runtime.h>
#include <math.h>

#define BSZ 16384
#define TN  10
#define IN_ 184
#define HN  128
#define HBS (TN*256)   // row stride (floats) between batch rows of layer outputs

// ---------------- scratch (static device globals; no allocation) ----------------
__device__ float g_out1[(size_t)BSZ * TN * 256];
__device__ float g_out2[(size_t)BSZ * TN * 256];
__device__ float g_cf[(size_t)BSZ * HN];
__device__ float g_cb[(size_t)BSZ * HN];
__device__ float g_pooled[(size_t)BSZ * 512];

// ---------------- fused LSTM step: GEMM ([x_t | h_prev] @ [Wih;Whh]^T) + pointwise ----
// Block tile: 128 batch rows x (32 hidden units * 4 gates = 128 cols).
// Thread layout: 256 threads = (tx=tid&15, ty=tid>>4).
//   rows: ty*8 + i   (i<8)
//   cols: g*32 + 2*tx + uu  (g<4 gates, uu<2) -> acc[i][g*2+uu]
// grid = (BSZ/128, HN/32, 2 dirs)
template<int KX>
__global__ __launch_bounds__(256, 2)
void lstm_step(
    const float* __restrict__ xf, const float* __restrict__ xb, int xbs,
    const float* __restrict__ Wih_f, const float* __restrict__ Whh_f,
    const float* __restrict__ bih_f, const float* __restrict__ bhh_f,
    const float* __restrict__ Wih_b, const float* __restrict__ Whh_b,
    const float* __restrict__ bih_b, const float* __restrict__ bhh_b,
    const float* __restrict__ hpf, const float* __restrict__ hpb,  // null at t==0
    float* __restrict__ cfb, float* __restrict__ cbb,
    float* __restrict__ out, int tout_f, int tout_b, int first)
{
    const int dir = blockIdx.z;
    const float* __restrict__ xs   = dir ? xb    : xf;
    const float* __restrict__ Wih  = dir ? Wih_b : Wih_f;
    const float* __restrict__ Whh  = dir ? Whh_b : Whh_f;
    const float* __restrict__ bih  = dir ? bih_b : bih_f;
    const float* __restrict__ bhh  = dir ? bhh_b : bhh_f;
    const float* __restrict__ hprev= dir ? hpb   : hpf;
    float* __restrict__ cbuf = dir ? cbb : cfb;
    const int tout = dir ? tout_b : tout_f;

    const int n0 = blockIdx.y * 32;
    const int b0 = blockIdx.x * 128;
    const int tid = threadIdx.x;
    const int tx = tid & 15, ty = tid >> 4;

    __shared__ float As[16][132];
    __shared__ float Bs[16][132];
    __shared__ float sBias[128];

    if (tid < 128) {
        int g = tid >> 5, m = tid & 31;
        int row = g * HN + n0 + m;
        sBias[tid] = bih[row] + bhh[row];
    }

    float acc[8][8];
#pragma unroll
    for (int i = 0; i < 8; ++i)
#pragma unroll
        for (int j = 0; j < 8; ++j) acc[i][j] = 0.f;

    const int KT = KX + HN;
    const int NT = (KT + 15) / 16;

    for (int kt = 0; kt < NT; ++kt) {
        const int kk = tid & 15;
        const int k  = kt * 16 + kk;
        const int lbase = tid >> 4;
        // load A tile (inputs): [x_t | h_prev]
#pragma unroll
        for (int i = 0; i < 8; ++i) {
            int bl = lbase + 16 * i;
            float v = 0.f;
            if (k < KX)      v = xs[(long)(b0 + bl) * xbs + k];
            else if (k < KT) v = hprev ? hprev[(long)(b0 + bl) * HBS + (k - KX)] : 0.f;
            As[kk][bl] = v;
        }
        // load B tile (weights): rows = g*HN + n0 + m for local col g*32+m
#pragma unroll
        for (int i = 0; i < 8; ++i) {
            int cl = lbase + 16 * i;
            int g = cl >> 5, m = cl & 31;
            int row = g * HN + n0 + m;
            float v = 0.f;
            if (k < KX)      v = Wih[(long)row * KX + k];
            else if (k < KT) v = Whh[(long)row * HN + (k - KX)];
            Bs[kk][cl] = v;
        }
        __syncthreads();
#pragma unroll
        for (int p = 0; p < 16; ++p) {
            float a[8], bb[8];
            float4 a0 = *(const float4*)&As[p][ty * 8];
            float4 a1 = *(const float4*)&As[p][ty * 8 + 4];
            a[0]=a0.x; a[1]=a0.y; a[2]=a0.z; a[3]=a0.w;
            a[4]=a1.x; a[5]=a1.y; a[6]=a1.z; a[7]=a1.w;
#pragma unroll
            for (int g = 0; g < 4; ++g) {
                float2 bv = *(const float2*)&Bs[p][g * 32 + 2 * tx];
                bb[g*2] = bv.x; bb[g*2+1] = bv.y;
            }
#pragma unroll
            for (int i = 0; i < 8; ++i)
#pragma unroll
                for (int j = 0; j < 8; ++j)
                    acc[i][j] = fmaf(a[i], bb[j], acc[i][j]);
        }
        __syncthreads();
    }

    // epilogue: LSTM pointwise for 2 hidden units (2*tx, 2*tx+1), 8 batch rows
    const int nbase = n0 + 2 * tx;
#pragma unroll
    for (int i = 0; i < 8; ++i) {
        const int b = b0 + ty * 8 + i;
        float hv[2];
#pragma unroll
        for (int uu = 0; uu < 2; ++uu) {
            const int cl = 2 * tx + uu;
            float vi = acc[i][0 + uu] + sBias[cl];
            float vf = acc[i][2 + uu] + sBias[32 + cl];
            float vg = acc[i][4 + uu] + sBias[64 + cl];
            float vo = acc[i][6 + uu] + sBias[96 + cl];
            float ig = 1.f / (1.f + __expf(-vi));
            float fg = 1.f / (1.f + __expf(-vf));
            float gg = tanhf(vg);
            float og = 1.f / (1.f + __expf(-vo));
            float cp = first ? 0.f : cbuf[(long)b * HN + nbase + uu];
            float cn = fg * cp + ig * gg;
            cbuf[(long)b * HN + nbase + uu] = cn;
            hv[uu] = og * tanhf(cn);
        }
        float2* po = (float2*)&out[((long)b * TN + tout) * 256 + dir * HN + nbase];
        *po = make_float2(hv[0], hv[1]);
    }
}

// ---------------- temporal max-pool: pooled[b, h*2+p] = max_s out2[b, p*5+s, h] ---
__global__ void pool_kernel(const float* __restrict__ out2, float* __restrict__ pooled)
{
    long idx = (long)blockIdx.x * blockDim.x + threadIdx.x;
    if (idx >= (long)BSZ * 512) return;
    int b = (int)(idx >> 9);
    int col = (int)(idx & 511);
    int h = col >> 1, p = col & 1;
    const float* base = out2 + (long)b * HBS + (long)(p * 5) * 256 + h;
    float m = base[0];
#pragma unroll
    for (int s = 1; s < 5; ++s) m = fmaxf(m, base[(long)s * 256]);
    pooled[idx] = m;
}

// ---------------- fused FC1(relu)+FC2: block = 64 batch rows -----------------------
__global__ __launch_bounds__(256)
void fc_kernel(const float* __restrict__ pooled,
               const float* __restrict__ w1, const float* __restrict__ b1,
               const float* __restrict__ w2, const float* __restrict__ b2,
               float* __restrict__ outp)
{
    __shared__ float S[64 * 65 + 64 * 64];
    float (*Ws)[65] = (float (*)[65])S;               // [k][o]
    float (*Ps)[64] = (float (*)[64])(S + 64 * 65);   // [bl][k]

    const int tid = threadIdx.x;
    const int b0 = blockIdx.x * 64;
    const int o  = tid & 63;
    const int tg = tid >> 6;   // 0..3

    float acc[16];
#pragma unroll
    for (int r = 0; r < 16; ++r) acc[r] = 0.f;

    for (int kt = 0; kt < 512; kt += 64) {
        for (int e = tid; e < 64 * 64; e += 256) {
            int oo = e >> 6, k = e & 63;
            Ws[k][oo] = w1[(long)oo * 512 + kt + k];
            int bl = oo;
            Ps[bl][k] = pooled[(long)(b0 + bl) * 512 + kt + k];
        }
        __syncthreads();
#pragma unroll 4
        for (int k = 0; k < 64; ++k) {
            float w = Ws[k][o];
#pragma unroll
            for (int r = 0; r < 16; ++r) {
                int bl = tg * 16 + r;
                acc[r] = fmaf(Ps[bl][k], w, acc[r]);
            }
        }
        __syncthreads();
    }

    // H1 overlaps Ws region (done with it)
    float (*H1)[65] = (float (*)[65])S;
    float bias1 = b1[o];
#pragma unroll
    for (int r = 0; r < 16; ++r) {
        int bl = tg * 16 + r;
        H1[bl][o] = fmaxf(acc[r] + bias1, 0.f);
    }
    __syncthreads();

    if (tid < 64) {
        float a2 = b2[0];
#pragma unroll
        for (int oo = 0; oo < 64; ++oo) a2 = fmaf(H1[tid][oo], w2[oo], a2);
        outp[b0 + tid] = a2;
    }
}

// ---------------- host launcher ----------------------------------------------------
extern "C" void kernel_launch(void* const* d_in, const int* in_sizes, int n_in,
                              void* d_out, int out_size)
{
    const float* x       = (const float*)d_in[0];
    const float* w_ih1_f = (const float*)d_in[1];
    const float* w_hh1_f = (const float*)d_in[2];
    const float* b_ih1_f = (const float*)d_in[3];
    const float* b_hh1_f = (const float*)d_in[4];
    const float* w_ih1_b = (const float*)d_in[5];
    const float* w_hh1_b = (const float*)d_in[6];
    const float* b_ih1_b = (const float*)d_in[7];
    const float* b_hh1_b = (const float*)d_in[8];
    const float* w_ih2_f = (const float*)d_in[9];
    const float* w_hh2_f = (const float*)d_in[10];
    const float* b_ih2_f = (const float*)d_in[11];
    const float* b_hh2_f = (const float*)d_in[12];
    const float* w_ih2_b = (const float*)d_in[13];
    const float* w_hh2_b = (const float*)d_in[14];
    const float* b_ih2_b = (const float*)d_in[15];
    const float* b_hh2_b = (const float*)d_in[16];
    const float* fc1_w   = (const float*)d_in[17];
    const float* fc1_b   = (const float*)d_in[18];
    const float* fc2_w   = (const float*)d_in[19];
    const float* fc2_b   = (const float*)d_in[20];

    float *out1, *out2, *cf, *cb, *pooled;
    cudaGetSymbolAddress((void**)&out1,   g_out1);
    cudaGetSymbolAddress((void**)&out2,   g_out2);
    cudaGetSymbolAddress((void**)&cf,     g_cf);
    cudaGetSymbolAddress((void**)&cb,     g_cb);
    cudaGetSymbolAddress((void**)&pooled, g_pooled);

    dim3 grid(BSZ / 128, HN / 32, 2), blk(256);

    // Layer 1: input x [B, T, 184]
    for (int t = 0; t < TN; ++t) {
        const float* xf = x + (long)t * IN_;
        const float* xb = x + (long)(TN - 1 - t) * IN_;
        const float* hpf = t ? out1 + (long)(t - 1) * 256       : nullptr;
        const float* hpb = t ? out1 + (long)(TN - t) * 256 + HN : nullptr;
        lstm_step<IN_><<<grid, blk>>>(xf, xb, TN * IN_,
            w_ih1_f, w_hh1_f, b_ih1_f, b_hh1_f,
            w_ih1_b, w_hh1_b, b_ih1_b, b_hh1_b,
            hpf, hpb, cf, cb, out1, t, TN - 1 - t, t == 0);
    }
    // Layer 2: input out1 [B, T, 256]
    for (int t = 0; t < TN; ++t) {
        const float* xf = out1 + (long)t * 256;
        const float* xb = out1 + (long)(TN - 1 - t) * 256;
        const float* hpf = t ? out2 + (long)(t - 1) * 256       : nullptr;
        const float* hpb = t ? out2 + (long)(TN - t) * 256 + HN : nullptr;
        lstm_step<256><<<grid, blk>>>(xf, xb, HBS,
            w_ih2_f, w_hh2_f, b_ih2_f, b_hh2_f,
            w_ih2_b, w_hh2_b, b_ih2_b, b_hh2_b,
            hpf, hpb, cf, cb, out2, t, TN - 1 - t, t == 0);
    }

    pool_kernel<<<((long)BSZ * 512 + 255) / 256, 256>>>(out2, pooled);
    fc_kernel<<<BSZ / 64, 256>>>(pooled, fc1_w, fc1_b, fc2_w, fc2_b, (float*)d_out);
}

// round 6
// speedup vs baseline: 2.6944x; 2.6944x over previous
#include <cuda_runtime.h>
#include <cuda_bf16.h>
#include <cstdint>
#include <math.h>

#define BSZ 16384
#define TN  10
#define IN_ 184
#define HN  128
#define WST 384          // weight-cat row stride (bf16 elems)

// ------------------------- scratch (__device__ globals) -------------------------
__device__ __nv_bfloat16 g_xh[(size_t)BSZ * TN * 192];
__device__ __nv_bfloat16 g_xl[(size_t)BSZ * TN * 192];
__device__ __nv_bfloat16 g_o1h[(size_t)BSZ * TN * 256];
__device__ __nv_bfloat16 g_o1l[(size_t)BSZ * TN * 256];
__device__ __nv_bfloat16 g_o2h[(size_t)BSZ * TN * 256];
__device__ __nv_bfloat16 g_o2l[(size_t)BSZ * TN * 256];
__device__ __nv_bfloat16 g_wh[(size_t)4 * 512 * WST];
__device__ __nv_bfloat16 g_wl[(size_t)4 * 512 * WST];
__device__ float g_cf[(size_t)BSZ * HN];
__device__ float g_cb[(size_t)BSZ * HN];
__device__ float g_pooled[(size_t)BSZ * 512];

// ------------------------- small helpers -------------------------
__device__ __forceinline__ uint32_t smem_u32(const void* p) {
    uint32_t a;
    asm("{ .reg .u64 t; cvta.to.shared.u64 t, %1; cvt.u32.u64 %0, t; }" : "=r"(a) : "l"(p));
    return a;
}
__device__ __forceinline__ void ldsm_x4(uint32_t& r0, uint32_t& r1, uint32_t& r2, uint32_t& r3, uint32_t addr) {
    asm volatile("ldmatrix.sync.aligned.m8n8.x4.shared.b16 {%0,%1,%2,%3}, [%4];"
                 : "=r"(r0), "=r"(r1), "=r"(r2), "=r"(r3) : "r"(addr));
}
__device__ __forceinline__ void ldsm_x2(uint32_t& r0, uint32_t& r1, uint32_t addr) {
    asm volatile("ldmatrix.sync.aligned.m8n8.x2.shared.b16 {%0,%1}, [%2];"
                 : "=r"(r0), "=r"(r1) : "r"(addr));
}
__device__ __forceinline__ void mma16816(float* d, const uint32_t* a, const uint32_t* b) {
    asm volatile("mma.sync.aligned.m16n8k16.row.col.f32.bf16.bf16.f32 "
                 "{%0,%1,%2,%3}, {%4,%5,%6,%7}, {%8,%9}, {%0,%1,%2,%3};"
                 : "+f"(d[0]), "+f"(d[1]), "+f"(d[2]), "+f"(d[3])
                 : "r"(a[0]), "r"(a[1]), "r"(a[2]), "r"(a[3]), "r"(b[0]), "r"(b[1]));
}

// ------------------------- split conversions -------------------------
__global__ void split_x_kernel(const float* __restrict__ x,
                               __nv_bfloat16* __restrict__ xh, __nv_bfloat16* __restrict__ xl) {
    long i = (long)blockIdx.x * blockDim.x + threadIdx.x;
    if (i >= (long)BSZ * TN * 192) return;
    int col = (int)(i % 192);
    long bt = i / 192;
    float v = (col < IN_) ? x[bt * IN_ + col] : 0.f;
    __nv_bfloat16 h = __float2bfloat16(v);
    xh[i] = h;
    xl[i] = __float2bfloat16(v - __bfloat162float(h));
}

__global__ void split_w_kernel(const float* __restrict__ a0, const float* __restrict__ h0,
                               const float* __restrict__ a1, const float* __restrict__ h1,
                               const float* __restrict__ a2, const float* __restrict__ h2,
                               const float* __restrict__ a3, const float* __restrict__ h3,
                               __nv_bfloat16* __restrict__ wh, __nv_bfloat16* __restrict__ wl) {
    long i = (long)blockIdx.x * blockDim.x + threadIdx.x;
    if (i >= (long)4 * 512 * WST) return;
    int col = (int)(i % WST);
    int r = (int)((i / WST) % 512);
    int cfg = (int)(i / ((long)512 * WST));
    const float* wih; const float* whh; int kx, hoff;
    switch (cfg) {
        case 0: wih = a0; whh = h0; kx = 184; hoff = 192; break;
        case 1: wih = a1; whh = h1; kx = 184; hoff = 192; break;
        case 2: wih = a2; whh = h2; kx = 256; hoff = 256; break;
        default: wih = a3; whh = h3; kx = 256; hoff = 256; break;
    }
    float v = 0.f;
    if (col < kx)                             v = wih[(long)r * kx + col];
    else if (col >= hoff && col < hoff + 128) v = whh[(long)r * 128 + (col - hoff)];
    __nv_bfloat16 h = __float2bfloat16(v);
    wh[i] = h;
    wl[i] = __float2bfloat16(v - __bfloat162float(h));
}

// ------------------------- fused HMMA LSTM step -------------------------
// Block: 128 batch rows x 128 cols (32 hidden units x 4 gates, col = 4*unit + gate).
// 256 threads = 8 warps in 2(m) x 4(n); warp tile 64 x 32.
// 3 bf16 hi/lo combos accumulate into fp32 mma accumulators.
struct DirP {
    const __nv_bfloat16 *axh, *axl;   // x-part base (offset to this step's t)
    const __nv_bfloat16 *ahh, *ahl;   // h-part base; unused if first
    const __nv_bfloat16 *wh, *wl;     // weight-cat [512][WST]
    const float *bih, *bhh;
    float* cbuf;
    __nv_bfloat16 *oh, *ol;           // out base (offset to t + dir col)
    long xstride, hstride, ostride;   // in elements
    int xchunks, nchunks;
};
struct StepP { DirP d[2]; int first; };

#define LDA 72                         // padded smem row stride (bf16 elems)
#define TILE_B (128 * LDA)             // elems per tile
#define SMEM_DYN (4 * TILE_B * 2 + 512)

__global__ __launch_bounds__(256, 2)
void lstm_mma(StepP sp)
{
    extern __shared__ char dyn[];
    __nv_bfloat16* sAh = (__nv_bfloat16*)dyn;
    __nv_bfloat16* sAl = sAh + TILE_B;
    __nv_bfloat16* sBh = sAl + TILE_B;
    __nv_bfloat16* sBl = sBh + TILE_B;
    float* sBias = (float*)(dyn + 4 * TILE_B * 2);
    const uint32_t sb = smem_u32(dyn);
    const uint32_t uAh = sb, uAl = sb + TILE_B * 2, uBh = sb + 2 * TILE_B * 2, uBl = sb + 3 * TILE_B * 2;

    const DirP& P = sp.d[blockIdx.z];
    const int first = sp.first;
    const int tid = threadIdx.x, lane = tid & 31, warp = tid >> 5;
    const int wm = warp >> 2, wn = warp & 3;          // warp grid 2 x 4
    const int b0 = blockIdx.x * 128, n0 = blockIdx.y * 32;

    // biases: sBias[4*u + g] = bih + bhh at weight row g*128 + n0 + u
    if (tid < 128) {
        int u = tid >> 2, g = tid & 3;
        int wr = g * 128 + n0 + u;
        sBias[tid] = P.bih[wr] + P.bhh[wr];
    }

    float acc[4][4][4];
#pragma unroll
    for (int i = 0; i < 4; ++i)
#pragma unroll
        for (int j = 0; j < 4; ++j)
#pragma unroll
            for (int k = 0; k < 4; ++k) acc[i][j][k] = 0.f;

    const int nc = first ? P.xchunks : P.nchunks;

    // ldmatrix lane-address components (hoisted)
    const int aRow = (lane & 15), aKo = (lane >> 4) * 8;
    const int bRow = (lane & 7),  bKo = ((lane >> 3) & 1) * 8;

    for (int c = 0; c < nc; ++c) {
        // ---- load 4 tiles global -> smem (16B granules) ----
        {
            const bool isx = (c < P.xchunks);
            const long acol = (long)(isx ? c : (c - P.xchunks)) * 64;
            const long astr = isx ? P.xstride : P.hstride;
            const __nv_bfloat16* abh = isx ? P.axh : P.ahh;
            const __nv_bfloat16* abl = isx ? P.axl : P.ahl;
#pragma unroll
            for (int it = 0; it < 4; ++it) {
                int idx = tid + it * 256;            // 0..1023
                int row = idx >> 3, gc = idx & 7;    // gc: 16B granule in 64-col chunk
                long go = (long)(b0 + row) * astr + acol + gc * 8;
                uint32_t so = (uint32_t)row * LDA + gc * 8;
                *(uint4*)(sAh + so) = *(const uint4*)(abh + go);
                *(uint4*)(sAl + so) = *(const uint4*)(abl + go);
            }
#pragma unroll
            for (int it = 0; it < 4; ++it) {
                int idx = tid + it * 256;
                int cl = idx >> 3, gc = idx & 7;
                int wr = (cl & 3) * 128 + n0 + (cl >> 2);
                long go = (long)wr * WST + (long)c * 64 + gc * 8;
                uint32_t so = (uint32_t)cl * LDA + gc * 8;
                *(uint4*)(sBh + so) = *(const uint4*)(P.wh + go);
                *(uint4*)(sBl + so) = *(const uint4*)(P.wl + go);
            }
        }
        __syncthreads();

        // ---- 3 combos x 4 k16 steps of mma ----
#pragma unroll
        for (int combo = 0; combo < 3; ++combo) {
            const uint32_t aB = (combo == 2) ? uAl : uAh;
            const uint32_t bB = (combo == 1) ? uBl : uBh;
#pragma unroll
            for (int kk = 0; kk < 4; ++kk) {
                uint32_t a[4][4], b[4][2];
#pragma unroll
                for (int mi = 0; mi < 4; ++mi) {
                    uint32_t ad = aB + (((wm * 64 + mi * 16 + aRow) * LDA) + kk * 16 + aKo) * 2;
                    ldsm_x4(a[mi][0], a[mi][1], a[mi][2], a[mi][3], ad);
                }
#pragma unroll
                for (int ni = 0; ni < 4; ++ni) {
                    uint32_t bd = bB + (((wn * 32 + ni * 8 + bRow) * LDA) + kk * 16 + bKo) * 2;
                    ldsm_x2(b[ni][0], b[ni][1], bd);
                }
#pragma unroll
                for (int mi = 0; mi < 4; ++mi)
#pragma unroll
                    for (int ni = 0; ni < 4; ++ni)
                        mma16816(acc[mi][ni], a[mi], b[ni]);
            }
        }
        __syncthreads();
    }

    // ---- epilogue: pair-exchange gates, LSTM pointwise, write h (hi/lo) + c ----
    const bool odd = (lane & 1);
    const int rbase = lane >> 2;
    const int usub = (lane >> 1) & 1;
#pragma unroll
    for (int mi = 0; mi < 4; ++mi) {
#pragma unroll
        for (int ni = 0; ni < 4; ++ni) {
            float c0 = acc[mi][ni][0], c1 = acc[mi][ni][1], c2 = acc[mi][ni][2], c3 = acc[mi][ni][3];
            float s0 = __shfl_xor_sync(0xFFFFFFFFu, c0, 1);
            float s1 = __shfl_xor_sync(0xFFFFFFFFu, c1, 1);
            float s2 = __shfl_xor_sync(0xFFFFFFFFu, c2, 1);
            float s3 = __shfl_xor_sync(0xFFFFFFFFu, c3, 1);
            float vi, vf, vg, vo;
            int r;
            if (!odd) { vi = c0; vf = c1; vg = s0; vo = s1; r = rbase; }
            else      { vi = s2; vf = s3; vg = c2; vo = c3; r = rbase + 8; }
            const int ul = ((wn * 32 + ni * 8) >> 2) + usub;       // unit local 0..31
            const float4 bb = *(const float4*)&sBias[4 * ul];
            vi += bb.x; vf += bb.y; vg += bb.z; vo += bb.w;
            float ig = 1.f / (1.f + __expf(-vi));
            float fg = 1.f / (1.f + __expf(-vf));
            float gg = tanhf(vg);
            float og = 1.f / (1.f + __expf(-vo));
            const long b = b0 + wm * 64 + mi * 16 + r;
            const int gu = n0 + ul;
            float cp = first ? 0.f : P.cbuf[b * HN + gu];
            float cn = fg * cp + ig * gg;
            P.cbuf[b * HN + gu] = cn;
            float h = og * tanhf(cn);
            __nv_bfloat16 hh = __float2bfloat16(h);
            P.oh[b * P.ostride + gu] = hh;
            P.ol[b * P.ostride + gu] = __float2bfloat16(h - __bfloat162float(hh));
        }
    }
}

// ------------------------- temporal max-pool -------------------------
__global__ void pool_kernel(const __nv_bfloat16* __restrict__ oh,
                            const __nv_bfloat16* __restrict__ ol,
                            float* __restrict__ pooled)
{
    long idx = (long)blockIdx.x * blockDim.x + threadIdx.x;
    if (idx >= (long)BSZ * 512) return;
    int b = (int)(idx >> 9);
    int col = (int)(idx & 511);
    int h = col >> 1, p = col & 1;
    long base = ((long)b * TN + p * 5) * 256 + h;
    float m = -1e30f;
#pragma unroll
    for (int s = 0; s < 5; ++s) {
        long i = base + (long)s * 256;
        float v = __bfloat162float(oh[i]) + __bfloat162float(ol[i]);
        m = fmaxf(m, v);
    }
    pooled[idx] = m;
}

// ------------------------- fused FC1(relu)+FC2 -------------------------
__global__ __launch_bounds__(256)
void fc_kernel(const float* __restrict__ pooled,
               const float* __restrict__ w1, const float* __restrict__ b1,
               const float* __restrict__ w2, const float* __restrict__ b2,
               float* __restrict__ outp)
{
    __shared__ float S[64 * 65 + 64 * 64];
    float (*Ws)[65] = (float (*)[65])S;
    float (*Ps)[64] = (float (*)[64])(S + 64 * 65);

    const int tid = threadIdx.x;
    const int b0 = blockIdx.x * 64;
    const int o  = tid & 63;
    const int tg = tid >> 6;

    float acc[16];
#pragma unroll
    for (int r = 0; r < 16; ++r) acc[r] = 0.f;

    for (int kt = 0; kt < 512; kt += 64) {
        for (int e = tid; e < 64 * 64; e += 256) {
            int oo = e >> 6, k = e & 63;
            Ws[k][oo] = w1[(long)oo * 512 + kt + k];
            Ps[oo][k] = pooled[(long)(b0 + oo) * 512 + kt + k];
        }
        __syncthreads();
#pragma unroll 4
        for (int k = 0; k < 64; ++k) {
            float w = Ws[k][o];
#pragma unroll
            for (int r = 0; r < 16; ++r)
                acc[r] = fmaf(Ps[tg * 16 + r][k], w, acc[r]);
        }
        __syncthreads();
    }
    float (*H1)[65] = (float (*)[65])S;
    float bias1 = b1[o];
#pragma unroll
    for (int r = 0; r < 16; ++r)
        H1[tg * 16 + r][o] = fmaxf(acc[r] + bias1, 0.f);
    __syncthreads();
    if (tid < 64) {
        float a2 = b2[0];
#pragma unroll
        for (int oo = 0; oo < 64; ++oo) a2 = fmaf(H1[tid][oo], w2[oo], a2);
        outp[b0 + tid] = a2;
    }
}

// ------------------------- host launcher -------------------------
extern "C" void kernel_launch(void* const* d_in, const int* in_sizes, int n_in,
                              void* d_out, int out_size)
{
    const float* x       = (const float*)d_in[0];
    const float* w_ih1_f = (const float*)d_in[1];
    const float* w_hh1_f = (const float*)d_in[2];
    const float* b_ih1_f = (const float*)d_in[3];
    const float* b_hh1_f = (const float*)d_in[4];
    const float* w_ih1_b = (const float*)d_in[5];
    const float* w_hh1_b = (const float*)d_in[6];
    const float* b_ih1_b = (const float*)d_in[7];
    const float* b_hh1_b = (const float*)d_in[8];
    const float* w_ih2_f = (const float*)d_in[9];
    const float* w_hh2_f = (const float*)d_in[10];
    const float* b_ih2_f = (const float*)d_in[11];
    const float* b_hh2_f = (const float*)d_in[12];
    const float* w_ih2_b = (const float*)d_in[13];
    const float* w_hh2_b = (const float*)d_in[14];
    const float* b_ih2_b = (const float*)d_in[15];
    const float* b_hh2_b = (const float*)d_in[16];
    const float* fc1_w   = (const float*)d_in[17];
    const float* fc1_b   = (const float*)d_in[18];
    const float* fc2_w   = (const float*)d_in[19];
    const float* fc2_b   = (const float*)d_in[20];

    __nv_bfloat16 *xh, *xl, *o1h, *o1l, *o2h, *o2l, *wh, *wl;
    float *cf, *cb, *pooled;
    cudaGetSymbolAddress((void**)&xh, g_xh);   cudaGetSymbolAddress((void**)&xl, g_xl);
    cudaGetSymbolAddress((void**)&o1h, g_o1h); cudaGetSymbolAddress((void**)&o1l, g_o1l);
    cudaGetSymbolAddress((void**)&o2h, g_o2h); cudaGetSymbolAddress((void**)&o2l, g_o2l);
    cudaGetSymbolAddress((void**)&wh, g_wh);   cudaGetSymbolAddress((void**)&wl, g_wl);
    cudaGetSymbolAddress((void**)&cf, g_cf);   cudaGetSymbolAddress((void**)&cb, g_cb);
    cudaGetSymbolAddress((void**)&pooled, g_pooled);

    cudaFuncSetAttribute(lstm_mma, cudaFuncAttributeMaxDynamicSharedMemorySize, SMEM_DYN);

    {
        long n = (long)BSZ * TN * 192;
        split_x_kernel<<<(unsigned)((n + 255) / 256), 256>>>(x, xh, xl);
        long m = (long)4 * 512 * WST;
        split_w_kernel<<<(unsigned)((m + 255) / 256), 256>>>(
            w_ih1_f, w_hh1_f, w_ih1_b, w_hh1_b, w_ih2_f, w_hh2_f, w_ih2_b, w_hh2_b, wh, wl);
    }

    dim3 grid(BSZ / 128, 4, 2), blk(256);
    const long WCFG = (long)512 * WST;

    // ---- layer 1 ----
    for (int t = 0; t < TN; ++t) {
        StepP sp;
        sp.first = (t == 0);
        sp.d[0].axh = xh + (long)t * 192;  sp.d[0].axl = xl + (long)t * 192;
        sp.d[0].ahh = t ? o1h + (long)(t - 1) * 256 : o1h;
        sp.d[0].ahl = t ? o1l + (long)(t - 1) * 256 : o1l;
        sp.d[0].wh = wh + 0 * WCFG; sp.d[0].wl = wl + 0 * WCFG;
        sp.d[0].bih = b_ih1_f; sp.d[0].bhh = b_hh1_f;
        sp.d[0].cbuf = cf;
        sp.d[0].oh = o1h + (long)t * 256; sp.d[0].ol = o1l + (long)t * 256;
        sp.d[0].xstride = (long)TN * 192; sp.d[0].hstride = (long)TN * 256; sp.d[0].ostride = (long)TN * 256;
        sp.d[0].xchunks = 3; sp.d[0].nchunks = 5;
        int tt = TN - 1 - t;
        sp.d[1].axh = xh + (long)tt * 192;  sp.d[1].axl = xl + (long)tt * 192;
        sp.d[1].ahh = t ? o1h + (long)(tt + 1) * 256 + HN : o1h;
        sp.d[1].ahl = t ? o1l + (long)(tt + 1) * 256 + HN : o1l;
        sp.d[1].wh = wh + 1 * WCFG; sp.d[1].wl = wl + 1 * WCFG;
        sp.d[1].bih = b_ih1_b; sp.d[1].bhh = b_hh1_b;
        sp.d[1].cbuf = cb;
        sp.d[1].oh = o1h + (long)tt * 256 + HN; sp.d[1].ol = o1l + (long)tt * 256 + HN;
        sp.d[1].xstride = (long)TN * 192; sp.d[1].hstride = (long)TN * 256; sp.d[1].ostride = (long)TN * 256;
        sp.d[1].xchunks = 3; sp.d[1].nchunks = 5;
        lstm_mma<<<grid, blk, SMEM_DYN>>>(sp);
    }

    // ---- layer 2 ----
    for (int t = 0; t < TN; ++t) {
        StepP sp;
        sp.first = (t == 0);
        sp.d[0].axh = o1h + (long)t * 256;  sp.d[0].axl = o1l + (long)t * 256;
        sp.d[0].ahh = t ? o2h + (long)(t - 1) * 256 : o2h;
        sp.d[0].ahl = t ? o2l + (long)(t - 1) * 256 : o2l;
        sp.d[0].wh = wh + 2 * WCFG; sp.d[0].wl = wl + 2 * WCFG;
        sp.d[0].bih = b_ih2_f; sp.d[0].bhh = b_hh2_f;
        sp.d[0].cbuf = cf;
        sp.d[0].oh = o2h + (long)t * 256; sp.d[0].ol = o2l + (long)t * 256;
        sp.d[0].xstride = (long)TN * 256; sp.d[0].hstride = (long)TN * 256; sp.d[0].ostride = (long)TN * 256;
        sp.d[0].xchunks = 4; sp.d[0].nchunks = 6;
        int tt = TN - 1 - t;
        sp.d[1].axh = o1h + (long)tt * 256;  sp.d[1].axl = o1l + (long)tt * 256;
        sp.d[1].ahh = t ? o2h + (long)(tt + 1) * 256 + HN : o2h;
        sp.d[1].ahl = t ? o2l + (long)(tt + 1) * 256 + HN : o2l;
        sp.d[1].wh = wh + 3 * WCFG; sp.d[1].wl = wl + 3 * WCFG;
        sp.d[1].bih = b_ih2_b; sp.d[1].bhh = b_hh2_b;
        sp.d[1].cbuf = cb;
        sp.d[1].oh = o2h + (long)tt * 256 + HN; sp.d[1].ol = o2l + (long)tt * 256 + HN;
        sp.d[1].xstride = (long)TN * 256; sp.d[1].hstride = (long)TN * 256; sp.d[1].ostride = (long)TN * 256;
        sp.d[1].xchunks = 4; sp.d[1].nchunks = 6;
        lstm_mma<<<grid, blk, SMEM_DYN>>>(sp);
    }

    pool_kernel<<<(unsigned)(((long)BSZ * 512 + 255) / 256), 256>>>(o2h, o2l, pooled);
    fc_kernel<<<BSZ / 64, 256>>>(pooled, fc1_w, fc1_b, fc2_w, fc2_b, (float*)d_out);
}

// round 9
// speedup vs baseline: 5.5146x; 2.0467x over previous
#include <cuda_runtime.h>
#include <cuda_bf16.h>
#include <cstdint>
#include <math.h>

#define BSZ 16384
#define TN  10
#define IN_ 184
#define HN  128
#define WST 384          // weight-cat row stride (bf16 elems)

// ------------------------- scratch (__device__ globals) -------------------------
__device__ __nv_bfloat16 g_xh[(size_t)BSZ * TN * 192];
__device__ __nv_bfloat16 g_xl[(size_t)BSZ * TN * 192];
__device__ __nv_bfloat16 g_o1h[(size_t)BSZ * TN * 256];
__device__ __nv_bfloat16 g_o1l[(size_t)BSZ * TN * 256];
__device__ __nv_bfloat16 g_o2h[(size_t)BSZ * TN * 256];
__device__ __nv_bfloat16 g_o2l[(size_t)BSZ * TN * 256];
__device__ __nv_bfloat16 g_wh[(size_t)4 * 512 * WST];
__device__ __nv_bfloat16 g_wl[(size_t)4 * 512 * WST];
__device__ float g_cf[(size_t)BSZ * HN];
__device__ float g_cb[(size_t)BSZ * HN];
__device__ float g_pooled[(size_t)BSZ * 512];

// ------------------------- small helpers -------------------------
__device__ __forceinline__ uint32_t smem_u32(const void* p) {
    uint32_t a;
    asm("{ .reg .u64 t; cvta.to.shared.u64 t, %1; cvt.u32.u64 %0, t; }" : "=r"(a) : "l"(p));
    return a;
}
__device__ __forceinline__ void ldsm_x4(uint32_t& r0, uint32_t& r1, uint32_t& r2, uint32_t& r3, uint32_t addr) {
    asm volatile("ldmatrix.sync.aligned.m8n8.x4.shared.b16 {%0,%1,%2,%3}, [%4];"
                 : "=r"(r0), "=r"(r1), "=r"(r2), "=r"(r3) : "r"(addr));
}
__device__ __forceinline__ void mma16816(float* d, const uint32_t* a, const uint32_t* b) {
    asm volatile("mma.sync.aligned.m16n8k16.row.col.f32.bf16.bf16.f32 "
                 "{%0,%1,%2,%3}, {%4,%5,%6,%7}, {%8,%9}, {%0,%1,%2,%3};"
                 : "+f"(d[0]), "+f"(d[1]), "+f"(d[2]), "+f"(d[3])
                 : "r"(a[0]), "r"(a[1]), "r"(a[2]), "r"(a[3]), "r"(b[0]), "r"(b[1]));
}

// ------------------------- split conversions -------------------------
__global__ void split_x_kernel(const float* __restrict__ x,
                               __nv_bfloat16* __restrict__ xh, __nv_bfloat16* __restrict__ xl) {
    long i = (long)blockIdx.x * blockDim.x + threadIdx.x;
    if (i >= (long)BSZ * TN * 192) return;
    int col = (int)(i % 192);
    long bt = i / 192;
    float v = (col < IN_) ? x[bt * IN_ + col] : 0.f;
    __nv_bfloat16 h = __float2bfloat16(v);
    xh[i] = h;
    xl[i] = __float2bfloat16(v - __bfloat162float(h));
}

__global__ void split_w_kernel(const float* __restrict__ a0, const float* __restrict__ h0,
                               const float* __restrict__ a1, const float* __restrict__ h1,
                               const float* __restrict__ a2, const float* __restrict__ h2,
                               const float* __restrict__ a3, const float* __restrict__ h3,
                               __nv_bfloat16* __restrict__ wh, __nv_bfloat16* __restrict__ wl) {
    long i = (long)blockIdx.x * blockDim.x + threadIdx.x;
    if (i >= (long)4 * 512 * WST) return;
    int col = (int)(i % WST);
    int r = (int)((i / WST) % 512);
    int cfg = (int)(i / ((long)512 * WST));
    const float* wih; const float* whh; int kx, hoff;
    switch (cfg) {
        case 0: wih = a0; whh = h0; kx = 184; hoff = 192; break;
        case 1: wih = a1; whh = h1; kx = 184; hoff = 192; break;
        case 2: wih = a2; whh = h2; kx = 256; hoff = 256; break;
        default: wih = a3; whh = h3; kx = 256; hoff = 256; break;
    }
    float v = 0.f;
    if (col < kx)                             v = wih[(long)r * kx + col];
    else if (col >= hoff && col < hoff + 128) v = whh[(long)r * 128 + (col - hoff)];
    __nv_bfloat16 h = __float2bfloat16(v);
    wh[i] = h;
    wl[i] = __float2bfloat16(v - __bfloat162float(h));
}

// ------------------------- fused HMMA LSTM step -------------------------
// Block: 128 batch rows x 128 cols (32 hidden units x 4 gates, col = 4*unit + gate).
// 256 threads = 8 warps in 2(m) x 4(n); warp tile 64 x 32.
// 3 bf16 hi/lo combos (AhWh + AhWl + AlWh) from register-resident fragments.
struct DirP {
    const __nv_bfloat16 *axh, *axl;
    const __nv_bfloat16 *ahh, *ahl;
    const __nv_bfloat16 *wh, *wl;
    const float *bih, *bhh;
    float* cbuf;
    __nv_bfloat16 *oh, *ol;
    long xstride, hstride, ostride;
    int xchunks, nchunks;
};
struct StepP { DirP d[2]; int first; };

#define LDA 72                         // padded smem row stride (bf16 elems)
#define TILE_B (128 * LDA)
#define SMEM_DYN (4 * TILE_B * 2 + 512)

__global__ __launch_bounds__(256, 2)
void lstm_mma(StepP sp)
{
    extern __shared__ char dyn[];
    float* sBias = (float*)(dyn + 4 * TILE_B * 2);
    const uint32_t sb = smem_u32(dyn);
    const uint32_t uAh = sb, uAl = sb + TILE_B * 2, uBh = sb + 2 * TILE_B * 2, uBl = sb + 3 * TILE_B * 2;
    __nv_bfloat16* sAh = (__nv_bfloat16*)dyn;
    __nv_bfloat16* sAl = sAh + TILE_B;
    __nv_bfloat16* sBh = sAl + TILE_B;
    __nv_bfloat16* sBl = sBh + TILE_B;

    const DirP& P = sp.d[blockIdx.z];
    const int first = sp.first;
    const int tid = threadIdx.x, lane = tid & 31, warp = tid >> 5;
    const int wm = warp >> 2, wn = warp & 3;          // warp grid 2 x 4
    const int b0 = blockIdx.x * 128, n0 = blockIdx.y * 32;

    if (tid < 128) {
        int u = tid >> 2, g = tid & 3;
        int wr = g * 128 + n0 + u;
        sBias[tid] = P.bih[wr] + P.bhh[wr];
    }

    float acc[4][4][4];
#pragma unroll
    for (int i = 0; i < 4; ++i)
#pragma unroll
        for (int j = 0; j < 4; ++j)
#pragma unroll
            for (int k = 0; k < 4; ++k) acc[i][j][k] = 0.f;

    const int nc = first ? P.xchunks : P.nchunks;

    // ldmatrix lane-address row/col components (hoisted)
    const int aRow = (lane & 15), aKo = (lane >> 4) * 8;          // A x4: 16 rows x 2 k-halves
    const int bRow = (lane & 7);                                  // B x4: 2 ni x 2 k-halves
    const int bKo  = ((lane >> 3) & 1) * 8;
    const int bNs  = ((lane >> 4) & 1) * 8;

    for (int c = 0; c < nc; ++c) {
        // ---- load 4 tiles global -> smem (16B granules) ----
        {
            const bool isx = (c < P.xchunks);
            const long acol = (long)(isx ? c : (c - P.xchunks)) * 64;
            const long astr = isx ? P.xstride : P.hstride;
            const __nv_bfloat16* abh = isx ? P.axh : P.ahh;
            const __nv_bfloat16* abl = isx ? P.axl : P.ahl;
#pragma unroll
            for (int it = 0; it < 4; ++it) {
                int idx = tid + it * 256;            // 0..1023
                int row = idx >> 3, gc = idx & 7;
                long go = (long)(b0 + row) * astr + acol + gc * 8;
                uint32_t so = (uint32_t)row * LDA + gc * 8;
                *(uint4*)(sAh + so) = *(const uint4*)(abh + go);
                *(uint4*)(sAl + so) = *(const uint4*)(abl + go);
            }
#pragma unroll
            for (int it = 0; it < 4; ++it) {
                int idx = tid + it * 256;
                int cl = idx >> 3, gc = idx & 7;
                int wr = (cl & 3) * 128 + n0 + (cl >> 2);
                long go = (long)wr * WST + (long)c * 64 + gc * 8;
                uint32_t so = (uint32_t)cl * LDA + gc * 8;
                *(uint4*)(sBh + so) = *(const uint4*)(P.wh + go);
                *(uint4*)(sBl + so) = *(const uint4*)(P.wl + go);
            }
        }
        __syncthreads();

        // ---- 4 k16 steps; fragments loaded ONCE, 3 combos from registers ----
#pragma unroll
        for (int kk = 0; kk < 4; ++kk) {
            const uint32_t aoff = ((uint32_t)(wm * 64 + aRow) * LDA + kk * 16 + aKo) * 2;
            uint32_t ah[4][4], al[4][4];
#pragma unroll
            for (int mi = 0; mi < 4; ++mi) {
                ldsm_x4(ah[mi][0], ah[mi][1], ah[mi][2], ah[mi][3], uAh + aoff + mi * 16 * LDA * 2);
                ldsm_x4(al[mi][0], al[mi][1], al[mi][2], al[mi][3], uAl + aoff + mi * 16 * LDA * 2);
            }
#pragma unroll
            for (int np = 0; np < 2; ++np) {         // ni pairs {0,1}, {2,3}
                const uint32_t boff = ((uint32_t)(wn * 32 + np * 16 + bNs + bRow) * LDA + kk * 16 + bKo) * 2;
                uint32_t bh[4], bl[4];
                ldsm_x4(bh[0], bh[1], bh[2], bh[3], uBh + boff);
                ldsm_x4(bl[0], bl[1], bl[2], bl[3], uBl + boff);
#pragma unroll
                for (int mi = 0; mi < 4; ++mi) {
                    mma16816(acc[mi][np * 2 + 0], ah[mi], bh + 0);
                    mma16816(acc[mi][np * 2 + 0], al[mi], bh + 0);
                    mma16816(acc[mi][np * 2 + 0], ah[mi], bl + 0);
                    mma16816(acc[mi][np * 2 + 1], ah[mi], bh + 2);
                    mma16816(acc[mi][np * 2 + 1], al[mi], bh + 2);
                    mma16816(acc[mi][np * 2 + 1], ah[mi], bl + 2);
                }
            }
        }
        __syncthreads();
    }

    // ---- epilogue: pair-exchange gates, LSTM pointwise, write h (hi/lo) + c ----
    const bool odd = (lane & 1);
    const int rbase = lane >> 2;
    const int usub = (lane >> 1) & 1;
#pragma unroll
    for (int mi = 0; mi < 4; ++mi) {
#pragma unroll
        for (int ni = 0; ni < 4; ++ni) {
            float c0 = acc[mi][ni][0], c1 = acc[mi][ni][1], c2 = acc[mi][ni][2], c3 = acc[mi][ni][3];
            float s0 = __shfl_xor_sync(0xFFFFFFFFu, c0, 1);
            float s1 = __shfl_xor_sync(0xFFFFFFFFu, c1, 1);
            float s2 = __shfl_xor_sync(0xFFFFFFFFu, c2, 1);
            float s3 = __shfl_xor_sync(0xFFFFFFFFu, c3, 1);
            float vi, vf, vg, vo;
            int r;
            if (!odd) { vi = c0; vf = c1; vg = s0; vo = s1; r = rbase; }
            else      { vi = s2; vf = s3; vg = c2; vo = c3; r = rbase + 8; }
            const int ul = ((wn * 32 + ni * 8) >> 2) + usub;
            const float4 bb = *(const float4*)&sBias[4 * ul];
            vi += bb.x; vf += bb.y; vg += bb.z; vo += bb.w;
            float ig = 1.f / (1.f + __expf(-vi));
            float fg = 1.f / (1.f + __expf(-vf));
            float gg = tanhf(vg);
            float og = 1.f / (1.f + __expf(-vo));
            const long b = b0 + wm * 64 + mi * 16 + r;
            const int gu = n0 + ul;
            float cp = first ? 0.f : P.cbuf[b * HN + gu];
            float cn = fg * cp + ig * gg;
            P.cbuf[b * HN + gu] = cn;
            float h = og * tanhf(cn);
            __nv_bfloat16 hh = __float2bfloat16(h);
            P.oh[b * P.ostride + gu] = hh;
            P.ol[b * P.ostride + gu] = __float2bfloat16(h - __bfloat162float(hh));
        }
    }
}

// ------------------------- temporal max-pool -------------------------
__global__ void pool_kernel(const __nv_bfloat16* __restrict__ oh,
                            const __nv_bfloat16* __restrict__ ol,
                            float* __restrict__ pooled)
{
    long idx = (long)blockIdx.x * blockDim.x + threadIdx.x;
    if (idx >= (long)BSZ * 512) return;
    int b = (int)(idx >> 9);
    int col = (int)(idx & 511);
    int h = col >> 1, p = col & 1;
    long base = ((long)b * TN + p * 5) * 256 + h;
    float m = -1e30f;
#pragma unroll
    for (int s = 0; s < 5; ++s) {
        long i = base + (long)s * 256;
        float v = __bfloat162float(oh[i]) + __bfloat162float(ol[i]);
        m = fmaxf(m, v);
    }
    pooled[idx] = m;
}

// ------------------------- fused FC1(relu)+FC2 -------------------------
__global__ __launch_bounds__(256)
void fc_kernel(const float* __restrict__ pooled,
               const float* __restrict__ w1, const float* __restrict__ b1,
               const float* __restrict__ w2, const float* __restrict__ b2,
               float* __restrict__ outp)
{
    __shared__ float S[64 * 65 + 64 * 64];
    float (*Ws)[65] = (float (*)[65])S;
    float (*Ps)[64] = (float (*)[64])(S + 64 * 65);

    const int tid = threadIdx.x;
    const int b0 = blockIdx.x * 64;
    const int o  = tid & 63;
    const int tg = tid >> 6;

    float acc[16];
#pragma unroll
    for (int r = 0; r < 16; ++r) acc[r] = 0.f;

    for (int kt = 0; kt < 512; kt += 64) {
        for (int e = tid; e < 64 * 64; e += 256) {
            int oo = e >> 6, k = e & 63;
            Ws[k][oo] = w1[(long)oo * 512 + kt + k];
            Ps[oo][k] = pooled[(long)(b0 + oo) * 512 + kt + k];
        }
        __syncthreads();
#pragma unroll 4
        for (int k = 0; k < 64; ++k) {
            float w = Ws[k][o];
#pragma unroll
            for (int r = 0; r < 16; ++r)
                acc[r] = fmaf(Ps[tg * 16 + r][k], w, acc[r]);
        }
        __syncthreads();
    }
    float (*H1)[65] = (float (*)[65])S;
    float bias1 = b1[o];
#pragma unroll
    for (int r = 0; r < 16; ++r)
        H1[tg * 16 + r][o] = fmaxf(acc[r] + bias1, 0.f);
    __syncthreads();
    if (tid < 64) {
        float a2 = b2[0];
#pragma unroll
        for (int oo = 0; oo < 64; ++oo) a2 = fmaf(H1[tid][oo], w2[oo], a2);
        outp[b0 + tid] = a2;
    }
}

// ------------------------- host launcher -------------------------
extern "C" void kernel_launch(void* const* d_in, const int* in_sizes, int n_in,
                              void* d_out, int out_size)
{
    const float* x       = (const float*)d_in[0];
    const float* w_ih1_f = (const float*)d_in[1];
    const float* w_hh1_f = (const float*)d_in[2];
    const float* b_ih1_f = (const float*)d_in[3];
    const float* b_hh1_f = (const float*)d_in[4];
    const float* w_ih1_b = (const float*)d_in[5];
    const float* w_hh1_b = (const float*)d_in[6];
    const float* b_ih1_b = (const float*)d_in[7];
    const float* b_hh1_b = (const float*)d_in[8];
    const float* w_ih2_f = (const float*)d_in[9];
    const float* w_hh2_f = (const float*)d_in[10];
    const float* b_ih2_f = (const float*)d_in[11];
    const float* b_hh2_f = (const float*)d_in[12];
    const float* w_ih2_b = (const float*)d_in[13];
    const float* w_hh2_b = (const float*)d_in[14];
    const float* b_ih2_b = (const float*)d_in[15];
    const float* b_hh2_b = (const float*)d_in[16];
    const float* fc1_w   = (const float*)d_in[17];
    const float* fc1_b   = (const float*)d_in[18];
    const float* fc2_w   = (const float*)d_in[19];
    const float* fc2_b   = (const float*)d_in[20];

    __nv_bfloat16 *xh, *xl, *o1h, *o1l, *o2h, *o2l, *wh, *wl;
    float *cf, *cb, *pooled;
    cudaGetSymbolAddress((void**)&xh, g_xh);   cudaGetSymbolAddress((void**)&xl, g_xl);
    cudaGetSymbolAddress((void**)&o1h, g_o1h); cudaGetSymbolAddress((void**)&o1l, g_o1l);
    cudaGetSymbolAddress((void**)&o2h, g_o2h); cudaGetSymbolAddress((void**)&o2l, g_o2l);
    cudaGetSymbolAddress((void**)&wh, g_wh);   cudaGetSymbolAddress((void**)&wl, g_wl);
    cudaGetSymbolAddress((void**)&cf, g_cf);   cudaGetSymbolAddress((void**)&cb, g_cb);
    cudaGetSymbolAddress((void**)&pooled, g_pooled);

    cudaFuncSetAttribute(lstm_mma, cudaFuncAttributeMaxDynamicSharedMemorySize, SMEM_DYN);

    {
        long n = (long)BSZ * TN * 192;
        split_x_kernel<<<(unsigned)((n + 255) / 256), 256>>>(x, xh, xl);
        long m = (long)4 * 512 * WST;
        split_w_kernel<<<(unsigned)((m + 255) / 256), 256>>>(
            w_ih1_f, w_hh1_f, w_ih1_b, w_hh1_b, w_ih2_f, w_hh2_f, w_ih2_b, w_hh2_b, wh, wl);
    }

    dim3 grid(BSZ / 128, 4, 2), blk(256);
    const long WCFG = (long)512 * WST;

    // ---- layer 1 ----
    for (int t = 0; t < TN; ++t) {
        StepP sp;
        sp.first = (t == 0);
        sp.d[0].axh = xh + (long)t * 192;  sp.d[0].axl = xl + (long)t * 192;
        sp.d[0].ahh = t ? o1h + (long)(t - 1) * 256 : o1h;
        sp.d[0].ahl = t ? o1l + (long)(t - 1) * 256 : o1l;
        sp.d[0].wh = wh + 0 * WCFG; sp.d[0].wl = wl + 0 * WCFG;
        sp.d[0].bih = b_ih1_f; sp.d[0].bhh = b_hh1_f;
        sp.d[0].cbuf = cf;
        sp.d[0].oh = o1h + (long)t * 256; sp.d[0].ol = o1l + (long)t * 256;
        sp.d[0].xstride = (long)TN * 192; sp.d[0].hstride = (long)TN * 256; sp.d[0].ostride = (long)TN * 256;
        sp.d[0].xchunks = 3; sp.d[0].nchunks = 5;
        int tt = TN - 1 - t;
        sp.d[1].axh = xh + (long)tt * 192;  sp.d[1].axl = xl + (long)tt * 192;
        sp.d[1].ahh = t ? o1h + (long)(tt + 1) * 256 + HN : o1h;
        sp.d[1].ahl = t ? o1l + (long)(tt + 1) * 256 + HN : o1l;
        sp.d[1].wh = wh + 1 * WCFG; sp.d[1].wl = wl + 1 * WCFG;
        sp.d[1].bih = b_ih1_b; sp.d[1].bhh = b_hh1_b;
        sp.d[1].cbuf = cb;
        sp.d[1].oh = o1h + (long)tt * 256 + HN; sp.d[1].ol = o1l + (long)tt * 256 + HN;
        sp.d[1].xstride = (long)TN * 192; sp.d[1].hstride = (long)TN * 256; sp.d[1].ostride = (long)TN * 256;
        sp.d[1].xchunks = 3; sp.d[1].nchunks = 5;
        lstm_mma<<<grid, blk, SMEM_DYN>>>(sp);
    }

    // ---- layer 2 ----
    for (int t = 0; t < TN; ++t) {
        StepP sp;
        sp.first = (t == 0);
        sp.d[0].axh = o1h + (long)t * 256;  sp.d[0].axl = o1l + (long)t * 256;
        sp.d[0].ahh = t ? o2h + (long)(t - 1) * 256 : o2h;
        sp.d[0].ahl = t ? o2l + (long)(t - 1) * 256 : o2l;
        sp.d[0].wh = wh + 2 * WCFG; sp.d[0].wl = wl + 2 * WCFG;
        sp.d[0].bih = b_ih2_f; sp.d[0].bhh = b_hh2_f;
        sp.d[0].cbuf = cf;
        sp.d[0].oh = o2h + (long)t * 256; sp.d[0].ol = o2l + (long)t * 256;
        sp.d[0].xstride = (long)TN * 256; sp.d[0].hstride = (long)TN * 256; sp.d[0].ostride = (long)TN * 256;
        sp.d[0].xchunks = 4; sp.d[0].nchunks = 6;
        int tt = TN - 1 - t;
        sp.d[1].axh = o1h + (long)tt * 256;  sp.d[1].axl = o1l + (long)tt * 256;
        sp.d[1].ahh = t ? o2h + (long)(tt + 1) * 256 + HN : o2h;
        sp.d[1].ahl = t ? o2l + (long)(tt + 1) * 256 + HN : o2l;
        sp.d[1].wh = wh + 3 * WCFG; sp.d[1].wl = wl + 3 * WCFG;
        sp.d[1].bih = b_ih2_b; sp.d[1].bhh = b_hh2_b;
        sp.d[1].cbuf = cb;
        sp.d[1].oh = o2h + (long)tt * 256 + HN; sp.d[1].ol = o2l + (long)tt * 256 + HN;
        sp.d[1].xstride = (long)TN * 256; sp.d[1].hstride = (long)TN * 256; sp.d[1].ostride = (long)TN * 256;
        sp.d[1].xchunks = 4; sp.d[1].nchunks = 6;
        lstm_mma<<<grid, blk, SMEM_DYN>>>(sp);
    }

    pool_kernel<<<(unsigned)(((long)BSZ * 512 + 255) / 256), 256>>>(o2h, o2l, pooled);
    fc_kernel<<<BSZ / 64, 256>>>(pooled, fc1_w, fc1_b, fc2_w, fc2_b, (float*)d_out);
}